// round 10
// baseline (speedup 1.0000x reference)
#include <cuda_runtime.h>
#include <float.h>

// Density_loss: once-per-cloud x-sort, then 2-threads-per-query sorted kNN
// (left/right side split, side-local top-16 chains, bitonic-partner merge).
// B=8, N=2048, C=3, K=16.  d = |q|^2+|p|^2-2q.p (expansion form, fp32).

#define NPTS   2048
#define BATCH  8
#define CLOUDS (2 * BATCH)     // 16
#define KNN    16
#define QBLK   256             // queries per CTA
#define BLK    512             // 2 threads per query
#define TILES  (NPTS / QBLK)   // 8
#define WIN0   32              // initial regular per-side window
#define CHUNK  16
#define FULLM  0xffffffffu

// Sorted transformed points per cloud: {-2x, -2y, -2z, |p|^2}, ascending x.
__device__ float4 g_sorted[CLOUDS * NPTS];
__device__ float  g_partials[CLOUDS * TILES];

// ---------------------------------------------------------------------------
// Kernel 1: per-cloud bitonic sort by x. 1024 threads = one CE per thread.
// ---------------------------------------------------------------------------
__global__ __launch_bounds__(1024, 1)
void sort_kernel(const float* __restrict__ seed,
                 const float* __restrict__ gt) {
    __shared__ float          key[NPTS];
    __shared__ unsigned short idx[NPTS];

    const int cloud = blockIdx.x;          // which*8 + b
    const float* __restrict__ pts =
        ((cloud >> 3) == 0 ? seed : gt) + (size_t)(cloud & 7) * NPTS * 3;

    for (int i = threadIdx.x; i < NPTS; i += 1024) {
        key[i] = pts[3 * i];
        idx[i] = (unsigned short)i;
    }
    __syncthreads();

    const int t = threadIdx.x;             // exactly NPTS/2 CE workers
    for (int k = 2; k <= NPTS; k <<= 1) {
        for (int j = k >> 1; j > 0; j >>= 1) {
            const int i = ((t & ~(j - 1)) << 1) | (t & (j - 1));
            const int p = i | j;
            const bool up = ((i & k) == 0);
            const float a = key[i], c = key[p];
            if ((a > c) == up) {
                key[i] = c; key[p] = a;
                const unsigned short ta = idx[i];
                idx[i] = idx[p]; idx[p] = ta;
            }
            __syncthreads();
        }
    }

    for (int i = threadIdx.x; i < NPTS; i += 1024) {
        const int id = idx[i];
        const float x = pts[3 * id + 0];
        const float y = pts[3 * id + 1];
        const float z = pts[3 * id + 2];
        g_sorted[cloud * NPTS + i] =
            make_float4(-2.0f * x, -2.0f * y, -2.0f * z,
                        fmaf(x, x, fmaf(y, y, z * z)));
    }
}

// ---------------------------------------------------------------------------
// Kernel 2: kNN — 2 threads per query (side split), merged-sum epilogue.
// ---------------------------------------------------------------------------
__global__ __launch_bounds__(BLK, 1)
void knn_kernel() {
    __shared__ float4 sp[NPTS];            // 32 KB sorted transformed points
    __shared__ float  sred[BLK / 32];

    const int tile  = blockIdx.x;
    const int b     = blockIdx.y;
    const int which = blockIdx.z;
    const int cloud = which * BATCH + b;

    const float4* __restrict__ src = g_sorted + cloud * NPTS;
    for (int i = threadIdx.x; i < NPTS; i += BLK) sp[i] = src[i];
    __syncthreads();

    const int lane  = threadIdx.x & 31;
    const int side  = threadIdx.x & 1;                 // 0 = left, 1 = right
    const int qrank = tile * QBLK + (threadIdx.x >> 1);
    const float4 q  = sp[qrank];
    const float Qx  = -0.5f * q.x;                     // true x of query
    const float cx  = Qx;
    const float cy  = -0.5f * q.y;
    const float cz  = -0.5f * q.z;
    const float Qs  = q.w;

    float best[KNN];
#pragma unroll
    for (int k = 0; k < KNN; ++k) best[k] = FLT_MAX;
    float thresh = FLT_MAX;

    auto dist = [&](const float4 p) -> float {
        return fmaf(p.x, cx, fmaf(p.y, cy, fmaf(p.z, cz, Qs + p.w)));
    };
    auto insert = [&](float d) {
        if (__any_sync(FULLM, d < thresh)) {
            float v = (d < thresh) ? d : FLT_MAX;
#pragma unroll
            for (int k = 0; k < KNN; ++k) {
                const float lo = fminf(best[k], v);
                v       = fmaxf(best[k], v);
                best[k] = lo;
            }
            thresh = best[KNN - 1];
        }
    };

    // Rank of u-th candidate on this side: right = q+u (u=0 is self),
    // left = q-1-u.
    auto rank_of = [&](int u) -> int { return side ? (qrank + u) : (qrank - 1 - u); };
    auto in_range = [&](int j) -> bool { return (unsigned)j < (unsigned)NPTS; };

    // ---- Initial regular window: WIN0 candidates per side, no prune ----
#pragma unroll 4
    for (int u = 0; u < WIN0; ++u) {
        const int j  = rank_of(u);
        const int jc = in_range(j) ? j : qrank;
        float d = dist(sp[jc]);
        d = in_range(j) ? d : FLT_MAX;
        insert(d);
    }

    // ---- Chunked outward extension with per-chunk prune ----
    int off = WIN0;
    while (true) {
        // Tightened safe prune threshold: merged 16th <= min(own16, partner16).
        const float tp = fminf(thresh, __shfl_xor_sync(FULLM, thresh, 1));
        const int jf = rank_of(off);                   // frontier rank
        bool done = !in_range(jf);
        if (!done) {
            const float dx = Qx - (-0.5f * sp[jf].x);  // sign per side irrelevant
            done = (dx * dx >= tp);
        }
        if (__all_sync(FULLM, done)) break;

#pragma unroll
        for (int u = 0; u < CHUNK; ++u) {
            const int j  = rank_of(off + u);
            const int jc = in_range(j) ? j : qrank;
            float d = dist(sp[jc]);
            d = (in_range(j) && !done) ? d : FLT_MAX;
            insert(d);
        }
        off += CHUNK;
    }

    // ---- Merge the two sorted side lists: sum of 16 smallest of union ----
    // = sum_i min(A[i], B[15-i])  (bitonic split). Even lane accumulates.
    float s = 0.0f;
#pragma unroll
    for (int i = 0; i < KNN; ++i) {
        const float partner = __shfl_xor_sync(FULLM, best[KNN - 1 - i], 1);
        s += fminf(best[i], partner);
    }
    s *= (1.0f / KNN);
    if (side) s = 0.0f;                    // count each query once

    // ---- Deterministic block reduction ----
#pragma unroll
    for (int o = 16; o > 0; o >>= 1)
        s += __shfl_down_sync(FULLM, s, o);
    if (lane == 0) sred[threadIdx.x >> 5] = s;
    __syncthreads();
    if (threadIdx.x == 0) {
        float tt = 0.0f;
#pragma unroll
        for (int w = 0; w < BLK / 32; ++w) tt += sred[w];
        g_partials[cloud * TILES + tile] = tt;
    }
}

// ---------------------------------------------------------------------------
// Kernel 3: finalize MSE.
// ---------------------------------------------------------------------------
__global__ void finalize_kernel(float* __restrict__ out) {
    const int lane = threadIdx.x;   // 32 threads
    float s = 0.0f;
    if (lane < CLOUDS) {
        const int base = lane * TILES;       // lane = which*8 + b
#pragma unroll
        for (int t = 0; t < TILES; ++t) s += g_partials[base + t];
        s *= (1.0f / NPTS);
    }
    const float other = __shfl_xor_sync(FULLM, s, 8);   // pair seed<->gt
    const float diff = s - other;
    float d2 = diff * diff;
    if (lane >= 8) d2 = 0.0f;
#pragma unroll
    for (int o = 4; o > 0; o >>= 1)
        d2 += __shfl_down_sync(FULLM, d2, o);
    if (lane == 0) out[0] = d2 * (1.0f / BATCH);
}

extern "C" void kernel_launch(void* const* d_in, const int* in_sizes, int n_in,
                              void* d_out, int out_size) {
    const float* seed = (const float*)d_in[0];
    const float* gt_s = (const float*)d_in[1];
    float* out = (float*)d_out;

    sort_kernel<<<CLOUDS, 1024>>>(seed, gt_s);
    dim3 grid(TILES, BATCH, 2);
    knn_kernel<<<grid, BLK>>>();
    finalize_kernel<<<1, 32>>>(out);
}

// round 13
// speedup vs baseline: 1.1805x; 1.1805x over previous
#include <cuda_runtime.h>
#include <float.h>

// Density_loss: once-per-cloud x-sort (packed u64 bitonic), then sorted-order
// kNN scan with sentinel-padded SMEM (no bounds checks) and paired votes.
// B=8, N=2048, C=3, K=16.  d = |q|^2+|p|^2-2q.p (expansion form, fp32).

#define NPTS   2048
#define BATCH  8
#define CLOUDS (2 * BATCH)     // 16
#define KNN    16
#define QBLK   256             // queries per CTA
#define BLK    256             // 1 thread per query
#define TILES  (NPTS / QBLK)   // 8
#define WINP   64              // phase-A pairs: covers ranks q-64 .. q+63
#define CHUNK  32              // per-side candidates per prune step
#define PAD    2080            // sentinel pad each side (covers max overshoot)
#define FULLM  0xffffffffu

// Sorted transformed points per cloud: {-2x, -2y, -2z, |p|^2}, ascending x.
__device__ float4 g_sorted[CLOUDS * NPTS];
__device__ float  g_partials[CLOUDS * TILES];

// ---------------------------------------------------------------------------
// Kernel 1: per-cloud bitonic sort by x, key+idx packed into one u64.
// ---------------------------------------------------------------------------
__global__ __launch_bounds__(1024, 1)
void sort_kernel(const float* __restrict__ seed,
                 const float* __restrict__ gt) {
    __shared__ unsigned long long a[NPTS];

    const int cloud = blockIdx.x;          // which*8 + b
    const float* __restrict__ pts =
        ((cloud >> 3) == 0 ? seed : gt) + (size_t)(cloud & 7) * NPTS * 3;

    for (int i = threadIdx.x; i < NPTS; i += 1024) {
        const unsigned bits = __float_as_uint(pts[3 * i]);
        const unsigned mono =
            (bits & 0x80000000u) ? ~bits : (bits | 0x80000000u);
        a[i] = ((unsigned long long)mono << 32) | (unsigned)i;
    }
    __syncthreads();

    const int t = threadIdx.x;             // exactly NPTS/2 CE workers
    for (int k = 2; k <= NPTS; k <<= 1) {
        for (int j = k >> 1; j > 0; j >>= 1) {
            const int i = ((t & ~(j - 1)) << 1) | (t & (j - 1));
            const int p = i | j;
            const bool up = ((i & k) == 0);
            const unsigned long long A = a[i], B = a[p];
            if ((A > B) == up) { a[i] = B; a[p] = A; }
            __syncthreads();
        }
    }

    for (int i = threadIdx.x; i < NPTS; i += 1024) {
        const int id = (int)(a[i] & 0xFFFFFFFFu);
        const float x = pts[3 * id + 0];
        const float y = pts[3 * id + 1];
        const float z = pts[3 * id + 2];
        g_sorted[cloud * NPTS + i] =
            make_float4(-2.0f * x, -2.0f * y, -2.0f * z,
                        fmaf(x, x, fmaf(y, y, z * z)));
    }
}

// ---------------------------------------------------------------------------
// Kernel 2: kNN — sentinel-padded sorted scan, paired votes.
// Dynamic SMEM layout: [PAD sentinels | NPTS points | PAD sentinels].
// ---------------------------------------------------------------------------
extern __shared__ float4 dyn_smem[];

__global__ __launch_bounds__(BLK, 1)
void knn_kernel() {
    float4* const sp = dyn_smem + PAD;     // sp[-PAD .. NPTS+PAD)
    __shared__ float sred[BLK / 32];

    const int tile  = blockIdx.x;
    const int b     = blockIdx.y;
    const int which = blockIdx.z;
    const int cloud = which * BATCH + b;

    const float4* __restrict__ src = g_sorted + cloud * NPTS;
    for (int i = threadIdx.x; i < NPTS; i += BLK) sp[i] = src[i];
    // Sentinels: x = 1e19 -> distance ~1e38 (never inserts), dx^2 ~1e38
    // (immediately prunes). Sign irrelevant: prune compares dx*dx.
    const float4 sent = make_float4(-2e19f, 0.0f, 0.0f, 1e38f);
    for (int i = threadIdx.x; i < PAD; i += BLK) {
        dyn_smem[i]              = sent;   // left pad
        dyn_smem[PAD + NPTS + i] = sent;   // right pad
    }
    __syncthreads();

    const int lane  = threadIdx.x & 31;
    const int qrank = tile * QBLK + threadIdx.x;
    const float4 q  = sp[qrank];
    const float Qx  = -0.5f * q.x;         // true x of query
    const float cx  = Qx;
    const float cy  = -0.5f * q.y;
    const float cz  = -0.5f * q.z;
    const float Qs  = q.w;

    float best[KNN];
#pragma unroll
    for (int k = 0; k < KNN; ++k) best[k] = FLT_MAX;
    float thresh = FLT_MAX;

    auto dist = [&](const float4 p) -> float {
        return fmaf(p.x, cx, fmaf(p.y, cy, fmaf(p.z, cz, Qs + p.w)));
    };
    // One vote + one branch per TWO candidates. Gating the second chain with
    // the pre-update thresh is safe (superset); the chain discards rejects.
    auto pair_insert = [&](float d0, float d1) {
        if (__any_sync(FULLM, fminf(d0, d1) < thresh)) {
            float v = (d0 < thresh) ? d0 : FLT_MAX;
#pragma unroll
            for (int k = 0; k < KNN; ++k) {
                const float lo = fminf(best[k], v);
                v       = fmaxf(best[k], v);
                best[k] = lo;
            }
            float w = (d1 < thresh) ? d1 : FLT_MAX;
#pragma unroll
            for (int k = 0; k < KNN; ++k) {
                const float lo = fminf(best[k], w);
                w       = fmaxf(best[k], w);
                best[k] = lo;
            }
            thresh = best[KNN - 1];
        }
    };

    // ---- Phase A: regular symmetric window, ranks [q-WINP, q+WINP-1] ----
#pragma unroll 2
    for (int off = 0; off < WINP; ++off) {
        const float4 pr = sp[qrank + off];       // off=0 -> self (d ~ 0)
        const float4 pl = sp[qrank - 1 - off];
        pair_insert(dist(pl), dist(pr));
    }

    // ---- Phase B: extend left, chunked, per-lane frontier prune ----
    for (int off = WINP; off < NPTS; off += CHUNK) {
        const float xn  = -0.5f * sp[qrank - 1 - off].x;
        const float dx  = Qx - xn;
        if (__all_sync(FULLM, dx * dx >= thresh)) break;
#pragma unroll
        for (int u = 0; u < CHUNK; u += 2) {
            const float4 p0 = sp[qrank - 1 - off - u];
            const float4 p1 = sp[qrank - 2 - off - u];
            pair_insert(dist(p0), dist(p1));
        }
    }

    // ---- Phase C: extend right, chunked, per-lane frontier prune ----
    for (int off = WINP; off < NPTS; off += CHUNK) {
        const float xn  = -0.5f * sp[qrank + off].x;
        const float dx  = xn - Qx;
        if (__all_sync(FULLM, dx * dx >= thresh)) break;
#pragma unroll
        for (int u = 0; u < CHUNK; u += 2) {
            const float4 p0 = sp[qrank + off + u];
            const float4 p1 = sp[qrank + off + u + 1];
            pair_insert(dist(p0), dist(p1));
        }
    }

    // ---- Mean of 16 NN per point, deterministic block reduction ----
    float s = 0.0f;
#pragma unroll
    for (int k = 0; k < KNN; ++k) s += best[k];
    s *= (1.0f / KNN);

#pragma unroll
    for (int o = 16; o > 0; o >>= 1)
        s += __shfl_down_sync(FULLM, s, o);
    if (lane == 0) sred[threadIdx.x >> 5] = s;
    __syncthreads();
    if (threadIdx.x == 0) {
        float t = 0.0f;
#pragma unroll
        for (int w = 0; w < BLK / 32; ++w) t += sred[w];
        g_partials[cloud * TILES + tile] = t;
    }
}

// ---------------------------------------------------------------------------
// Kernel 3: finalize MSE.
// ---------------------------------------------------------------------------
__global__ void finalize_kernel(float* __restrict__ out) {
    const int lane = threadIdx.x;   // 32 threads
    float s = 0.0f;
    if (lane < CLOUDS) {
        const int base = lane * TILES;       // lane = which*8 + b
#pragma unroll
        for (int t = 0; t < TILES; ++t) s += g_partials[base + t];
        s *= (1.0f / NPTS);
    }
    const float other = __shfl_xor_sync(FULLM, s, 8);   // pair seed<->gt
    const float diff = s - other;
    float d2 = diff * diff;
    if (lane >= 8) d2 = 0.0f;
#pragma unroll
    for (int o = 4; o > 0; o >>= 1)
        d2 += __shfl_down_sync(FULLM, d2, o);
    if (lane == 0) out[0] = d2 * (1.0f / BATCH);
}

extern "C" void kernel_launch(void* const* d_in, const int* in_sizes, int n_in,
                              void* d_out, int out_size) {
    const float* seed = (const float*)d_in[0];
    const float* gt_s = (const float*)d_in[1];
    float* out = (float*)d_out;

    const size_t dyn_bytes = (size_t)(2 * PAD + NPTS) * sizeof(float4); // 99328
    cudaFuncSetAttribute(knn_kernel,
                         cudaFuncAttributeMaxDynamicSharedMemorySize,
                         (int)dyn_bytes);

    sort_kernel<<<CLOUDS, 1024>>>(seed, gt_s);
    dim3 grid(TILES, BATCH, 2);
    knn_kernel<<<grid, BLK, dyn_bytes>>>();
    finalize_kernel<<<1, 32>>>(out);
}